// round 16
// baseline (speedup 1.0000x reference)
#include <cuda_runtime.h>
#include <cuda_fp16.h>
#include <cstdint>
#include <math.h>

#define BDIM   1024
#define NHEAD  16
#define DHEAD  64
#define SEQ    2048
#define BATCH  2
#define NTOK   (BATCH * SEQ)      // 4096
#define HID    (4 * BDIM)         // 4096
#define EPSV   1e-6f

// ===================== helpers =============================================
__device__ __forceinline__ uint32_t smem_u32(const void* p) {
    uint32_t a;
    asm("{ .reg .u64 t; cvta.to.shared.u64 t, %1; cvt.u32.u64 %0, t; }"
        : "=r"(a) : "l"(p));
    return a;
}

#define CP_ASYNC16(s, g) \
    asm volatile("cp.async.cg.shared.global [%0], [%1], 16;" :: "r"(s), "l"(g))
#define CP_COMMIT()  asm volatile("cp.async.commit_group;" ::: "memory")
#define CP_WAIT1()   asm volatile("cp.async.wait_group 1;" ::: "memory")

#define LDSM4(r, a) \
    asm volatile("ldmatrix.sync.aligned.m8n8.x4.shared.b16 {%0,%1,%2,%3}, [%4];" \
        : "=r"((r)[0]), "=r"((r)[1]), "=r"((r)[2]), "=r"((r)[3]) : "r"(a))
#define LDSM4T(r, a) \
    asm volatile("ldmatrix.sync.aligned.m8n8.x4.trans.shared.b16 {%0,%1,%2,%3}, [%4];" \
        : "=r"((r)[0]), "=r"((r)[1]), "=r"((r)[2]), "=r"((r)[3]) : "r"(a))

#define MMA16816(d, a, b0, b1) \
    asm volatile("mma.sync.aligned.m16n8k16.row.col.f32.f16.f16.f32 " \
        "{%0,%1,%2,%3}, {%4,%5,%6,%7}, {%8,%9}, {%0,%1,%2,%3};" \
        : "+f"((d)[0]), "+f"((d)[1]), "+f"((d)[2]), "+f"((d)[3]) \
        : "r"((a)[0]), "r"((a)[1]), "r"((a)[2]), "r"((a)[3]), "r"(b0), "r"(b1))

__device__ __forceinline__ uint32_t packh2(float a, float b) {
    __half2 h = __floats2half2_rn(a, b);
    return *(uint32_t*)&h;
}

// ===================== scratch ==============================================
__device__ float g_x1 [(size_t)NTOK * BDIM];
__device__ unsigned short g_qkvh[(size_t)NTOK * 3 * BDIM];
__device__ unsigned short g_xnh[(size_t)NTOK * BDIM];
__device__ unsigned short g_ath[(size_t)NTOK * BDIM];
__device__ unsigned short g_hh [(size_t)NTOK * HID];
__device__ unsigned short g_wqkvh[(size_t)3 * BDIM * BDIM];
__device__ unsigned short g_woh[(size_t)BDIM * BDIM];
__device__ unsigned short g_wuph[(size_t)HID * BDIM];
__device__ unsigned short g_wgh [(size_t)HID * BDIM];
__device__ unsigned short g_wdh [(size_t)BDIM * HID];

// ===================== fused weight convert fp32 -> fp16 (16 elems/thread) ==
#define CX0 196608
#define CX1 (CX0 + 65536)
#define CX2 (CX1 + 262144)
#define CX3 (CX2 + 262144)
#define CX4 (CX3 + 262144)

__global__ void cvt_all(const float* __restrict__ wq, const float* __restrict__ wo,
                        const float* __restrict__ wu, const float* __restrict__ wg,
                        const float* __restrict__ wd,
                        __half* __restrict__ oq, __half* __restrict__ oo,
                        __half* __restrict__ ou, __half* __restrict__ og,
                        __half* __restrict__ od)
{
    int u = blockIdx.x * blockDim.x + threadIdx.x;
    if (u >= CX4) return;
    const float* in; __half* out; int base;
    if      (u < CX0) { in = wq; out = oq; base = 0;   }
    else if (u < CX1) { in = wo; out = oo; base = CX0; }
    else if (u < CX2) { in = wu; out = ou; base = CX1; }
    else if (u < CX3) { in = wg; out = og; base = CX2; }
    else              { in = wd; out = od; base = CX3; }
    int i16 = (u - base) * 16;
    float4 a = *(const float4*)(in + i16);
    float4 b = *(const float4*)(in + i16 + 4);
    float4 c = *(const float4*)(in + i16 + 8);
    float4 d = *(const float4*)(in + i16 + 12);
    uint4 o0, o1;
    o0.x = packh2(a.x, a.y); o0.y = packh2(a.z, a.w);
    o0.z = packh2(b.x, b.y); o0.w = packh2(b.z, b.w);
    o1.x = packh2(c.x, c.y); o1.y = packh2(c.z, c.w);
    o1.z = packh2(d.x, d.y); o1.w = packh2(d.z, d.w);
    *(uint4*)(out + i16)     = o0;
    *(uint4*)(out + i16 + 8) = o1;
}

// ===================== rmsnorm -> fp16 ======================================
__global__ void rmsnorm_h(const float* __restrict__ x,
                          const float* __restrict__ scale,
                          __half* __restrict__ ohi)
{
    int row = blockIdx.x;
    float4 v = ((const float4*)(x + (size_t)row * BDIM))[threadIdx.x];
    float ss = v.x * v.x + v.y * v.y + v.z * v.z + v.w * v.w;
    #pragma unroll
    for (int o = 16; o > 0; o >>= 1) ss += __shfl_xor_sync(0xffffffffu, ss, o);
    __shared__ float ws[8];
    if ((threadIdx.x & 31) == 0) ws[threadIdx.x >> 5] = ss;
    __syncthreads();
    float tot = ws[0] + ws[1] + ws[2] + ws[3] + ws[4] + ws[5] + ws[6] + ws[7];
    float inv = 1.0f / sqrtf(tot * (1.0f / BDIM) + EPSV);
    float4 sc = ((const float4*)scale)[threadIdx.x];
    size_t off = (size_t)row * BDIM + threadIdx.x * 4;
    *(__half2*)(ohi + off)     = __floats2half2_rn(v.x * inv * sc.x, v.y * inv * sc.y);
    *(__half2*)(ohi + off + 2) = __floats2half2_rn(v.z * inv * sc.z, v.w * inv * sc.w);
}

// ===================== HMMA fp16 GEMM (2 CTAs/SM, 3-stage) ==================
// C[M,N] = Ah[M,K] * Bh[N,K]^T ; fp32 accum.
// EPI 1: C(fp32) = acc + R ; EPI 3: O1(fp16) = acc
#define BM 128
#define BN 128
#define BKE 32
#define LDSB 80
#define BUF_B (BM * LDSB)           // 10240
#define STG_B (2 * BUF_B)           // 20480
#define NSTAGE 3
#define GEMM_SMEM (NSTAGE * STG_B)  // 61440

template<int EPI>
__global__ __launch_bounds__(256, 2)
void gemm_hmma(const __half* __restrict__ Ah, const __half* __restrict__ Bh,
               float* __restrict__ C, const float* __restrict__ R,
               __half* __restrict__ O1,
               int M, int N, int K)
{
    extern __shared__ char smem[];
    const uint32_t sb = smem_u32(smem);

    const int tid  = threadIdx.x;
    const int lane = tid & 31;
    const int wid  = tid >> 5;
    const int wm   = wid & 3;
    const int wn   = wid >> 2;
    const int bm = blockIdx.y * BM, bn = blockIdx.x * BN;

    const __half* gptr[2][2];
    uint32_t      sptr[2][2];
    {
        const __half* gsrc[2] = {Ah, Bh};
        #pragma unroll
        for (int q = 0; q < 2; q++) {
            int rbase = (q == 0) ? bm : bn;
            #pragma unroll
            for (int j = 0; j < 2; j++) {
                int idx = tid * 2 + j;
                int row = idx >> 2, kc = idx & 3;
                gptr[q][j] = gsrc[q] + (size_t)(rbase + row) * K + kc * 8;
                sptr[q][j] = sb + q * BUF_B + row * LDSB + kc * 16;
            }
        }
    }

    const int nch = K / BKE;

    #pragma unroll
    for (int s = 0; s < NSTAGE - 1; s++) {
        #pragma unroll
        for (int q = 0; q < 2; q++)
            #pragma unroll
            for (int j = 0; j < 2; j++)
                CP_ASYNC16(sptr[q][j] + s * STG_B, gptr[q][j] + s * BKE);
        CP_COMMIT();
    }

    const uint32_t pA = sb + (wm * 32 + (lane & 15)) * LDSB + ((lane >> 4) * 8) * 2;
    const int b_n = (lane & 7) + ((lane >> 4) & 1) * 8;
    const int b_k = ((lane >> 3) & 1) * 8;
    const uint32_t pB = sb + BUF_B + (wn * 64 + b_n) * LDSB + b_k * 2;

    float acc[2][8][4];
    #pragma unroll
    for (int i = 0; i < 2; i++)
        #pragma unroll
        for (int j = 0; j < 8; j++)
            #pragma unroll
            for (int r = 0; r < 4; r++) acc[i][j][r] = 0.0f;

    for (int c = 0; c < nch; c++) {
        CP_WAIT1();
        __syncthreads();

        const int cn = c + NSTAGE - 1;
        if (cn < nch) {
            const uint32_t sw = (cn % NSTAGE) * STG_B;
            #pragma unroll
            for (int q = 0; q < 2; q++)
                #pragma unroll
                for (int j = 0; j < 2; j++)
                    CP_ASYNC16(sptr[q][j] + sw, gptr[q][j] + cn * BKE);
        }
        CP_COMMIT();

        const uint32_t so = (c % NSTAGE) * STG_B;
        #pragma unroll
        for (int ks = 0; ks < 2; ks++) {
            uint32_t ah[2][4], bh[4][4];
            #pragma unroll
            for (int i = 0; i < 2; i++)
                LDSM4(ah[i], pA + so + i * (16 * LDSB) + ks * 32);
            #pragma unroll
            for (int j2 = 0; j2 < 4; j2++)
                LDSM4(bh[j2], pB + so + j2 * (16 * LDSB) + ks * 32);
            #pragma unroll
            for (int i = 0; i < 2; i++)
                #pragma unroll
                for (int j = 0; j < 8; j++) {
                    const int j2 = j >> 1, hh = (j & 1) * 2;
                    MMA16816(acc[i][j], ah[i], bh[j2][hh], bh[j2][hh + 1]);
                }
        }
    }

    const int g  = lane >> 2;
    const int c2 = (lane & 3) * 2;
    #pragma unroll
    for (int i = 0; i < 2; i++) {
        #pragma unroll
        for (int j = 0; j < 8; j++) {
            const int col = bn + wn * 64 + j * 8 + c2;
            const int r0 = bm + wm * 32 + i * 16 + g;
            #pragma unroll
            for (int hrow = 0; hrow < 2; hrow++) {
                const int row = r0 + hrow * 8;
                const size_t base = (size_t)row * N + col;
                float v0 = acc[i][j][hrow * 2 + 0];
                float v1 = acc[i][j][hrow * 2 + 1];
                if (EPI == 1) {
                    float2 rv = *(const float2*)(R + base);
                    *(float2*)(C + base) = make_float2(v0 + rv.x, v1 + rv.y);
                } else {
                    *(__half2*)(O1 + base) = __floats2half2_rn(v0, v1);
                }
            }
        }
    }
}

// ===================== fused up+gate GEMM (BN=64, 2 CTAs/SM, 3-stage) =======
#define UGN 64
#define UG_ABUF (BM * LDSB)                 // 10240
#define UG_BBUF (UGN * LDSB)                // 5120
#define UG_STG  (UG_ABUF + 2 * UG_BBUF)     // 20480
#define UG_NSTG 3
#define UG_SMEM (UG_NSTG * UG_STG)          // 61440

__global__ __launch_bounds__(256, 2)
void gemm_upgate(const __half* __restrict__ Ah, const __half* __restrict__ Bu,
                 const __half* __restrict__ Bg, __half* __restrict__ O1,
                 int M, int N, int K)
{
    extern __shared__ char smem[];
    const uint32_t sb = smem_u32(smem);

    const int tid  = threadIdx.x;
    const int lane = tid & 31;
    const int wid  = tid >> 5;
    const int wm   = wid & 3;
    const int wn   = wid >> 2;
    const int bm = blockIdx.y * BM, bn = blockIdx.x * UGN;

    const __half* gA[2]; uint32_t sA[2];
    #pragma unroll
    for (int j = 0; j < 2; j++) {
        int idx = tid * 2 + j;
        int row = idx >> 2, kc = idx & 3;
        gA[j] = Ah + (size_t)(bm + row) * K + kc * 8;
        sA[j] = sb + row * LDSB + kc * 16;
    }
    const int brow = tid >> 2, bkc = tid & 3;
    const __half* gBu = Bu + (size_t)(bn + brow) * K + bkc * 8;
    const __half* gBg = Bg + (size_t)(bn + brow) * K + bkc * 8;
    const uint32_t sBu = sb + UG_ABUF + brow * LDSB + bkc * 16;
    const uint32_t sBg = sb + UG_ABUF + UG_BBUF + brow * LDSB + bkc * 16;

    const int nch = K / BKE;

    #pragma unroll
    for (int s = 0; s < UG_NSTG - 1; s++) {
        #pragma unroll
        for (int j = 0; j < 2; j++) CP_ASYNC16(sA[j] + s * UG_STG, gA[j] + s * BKE);
        CP_ASYNC16(sBu + s * UG_STG, gBu + s * BKE);
        CP_ASYNC16(sBg + s * UG_STG, gBg + s * BKE);
        CP_COMMIT();
    }

    const uint32_t pA = sb + (wm * 32 + (lane & 15)) * LDSB + ((lane >> 4) * 8) * 2;
    const int b_n = (lane & 7) + ((lane >> 4) & 1) * 8;
    const int b_k = ((lane >> 3) & 1) * 8;
    const uint32_t pBu = sb + UG_ABUF + (wn * 32 + b_n) * LDSB + b_k * 2;
    const uint32_t pBg = pBu + UG_BBUF;

    float au[2][4][4], ag[2][4][4];
    #pragma unroll
    for (int i = 0; i < 2; i++)
        #pragma unroll
        for (int j = 0; j < 4; j++)
            #pragma unroll
            for (int r = 0; r < 4; r++) { au[i][j][r] = 0.0f; ag[i][j][r] = 0.0f; }

    for (int c = 0; c < nch; c++) {
        CP_WAIT1();
        __syncthreads();

        const int cn = c + UG_NSTG - 1;
        if (cn < nch) {
            const uint32_t sw = (cn % UG_NSTG) * UG_STG;
            #pragma unroll
            for (int j = 0; j < 2; j++) CP_ASYNC16(sA[j] + sw, gA[j] + cn * BKE);
            CP_ASYNC16(sBu + sw, gBu + cn * BKE);
            CP_ASYNC16(sBg + sw, gBg + cn * BKE);
        }
        CP_COMMIT();

        const uint32_t so = (c % UG_NSTG) * UG_STG;
        #pragma unroll
        for (int ks = 0; ks < 2; ks++) {
            uint32_t ah[2][4], bu[2][4], bg[2][4];
            #pragma unroll
            for (int i = 0; i < 2; i++)
                LDSM4(ah[i], pA + so + i * (16 * LDSB) + ks * 32);
            #pragma unroll
            for (int j2 = 0; j2 < 2; j2++) {
                LDSM4(bu[j2], pBu + so + j2 * (16 * LDSB) + ks * 32);
                LDSM4(bg[j2], pBg + so + j2 * (16 * LDSB) + ks * 32);
            }
            #pragma unroll
            for (int i = 0; i < 2; i++)
                #pragma unroll
                for (int j = 0; j < 4; j++) {
                    const int j2 = j >> 1, hh = (j & 1) * 2;
                    MMA16816(au[i][j], ah[i], bu[j2][hh], bu[j2][hh + 1]);
                    MMA16816(ag[i][j], ah[i], bg[j2][hh], bg[j2][hh + 1]);
                }
        }
    }

    const int g  = lane >> 2;
    const int c2 = (lane & 3) * 2;
    #pragma unroll
    for (int i = 0; i < 2; i++) {
        #pragma unroll
        for (int j = 0; j < 4; j++) {
            const int col = bn + wn * 32 + j * 8 + c2;
            const int r0 = bm + wm * 32 + i * 16 + g;
            #pragma unroll
            for (int hrow = 0; hrow < 2; hrow++) {
                const int row = r0 + hrow * 8;
                const size_t base = (size_t)row * N + col;
                float u0 = au[i][j][hrow * 2 + 0], u1 = au[i][j][hrow * 2 + 1];
                float g0 = ag[i][j][hrow * 2 + 0], g1 = ag[i][j][hrow * 2 + 1];
                float s0 = u0 * (g0 / (1.0f + __expf(-g0)));
                float s1 = u1 * (g1 / (1.0f + __expf(-g1)));
                *(__half2*)(O1 + base) = __floats2half2_rn(s0, s1);
            }
        }
    }
}

// ===================== fp16 HMMA flash attention =============================
// register prefetch + 2 CTAs/SM
#define AST 72

__global__ __launch_bounds__(256, 2)
void flash_attn_h(const __half* __restrict__ qkvh, __half* __restrict__ outh)
{
    __shared__ __half Qs[128][AST];
    __shared__ __half Ks[64][AST];
    __shared__ __half Vs[64][AST];

    const int qb = gridDim.x - 1 - blockIdx.x;
    const int hd = blockIdx.y, b = blockIdx.z;
    const int q0 = qb * 128;
    const int tid = threadIdx.x, lane = tid & 31, wid = tid >> 5;
    const int ld = 3 * BDIM;
    const int g = lane >> 2, c2 = lane & 3;

    const __half* qbase = qkvh + ((size_t)(b * SEQ + q0)) * ld + hd * DHEAD;
    #pragma unroll
    for (int i = 0; i < 4; i++) {
        int idx = tid + i * 256;
        int r = idx >> 3, c8 = (idx & 7) * 8;
        *(uint4*)&Qs[r][c8] = *(const uint4*)(qbase + (size_t)r * ld + c8);
    }

    const __half* kbase = qkvh + (size_t)(b * SEQ) * ld + BDIM     + hd * DHEAD;
    const __half* vbase = qkvh + (size_t)(b * SEQ) * ld + 2 * BDIM + hd * DHEAD;

    const int lr = tid >> 3;
    const int lc = (tid & 7) * 8;

    uint4 kr0 = *(const uint4*)(kbase + (size_t)lr * ld + lc);
    uint4 kr1 = *(const uint4*)(kbase + (size_t)(lr + 32) * ld + lc);
    uint4 vr0 = *(const uint4*)(vbase + (size_t)lr * ld + lc);
    uint4 vr1 = *(const uint4*)(vbase + (size_t)(lr + 32) * ld + lc);

    float o[8][4];
    #pragma unroll
    for (int j = 0; j < 8; j++)
        #pragma unroll
        for (int r = 0; r < 4; r++) o[j][r] = 0.0f;
    float mrow[2] = {-1e30f, -1e30f}, lsum[2] = {0.0f, 0.0f};

    const uint32_t qaddr = smem_u32(&Qs[wid * 16 + (lane & 15)][(lane >> 4) * 8]);
    const uint32_t kaddr = smem_u32(&Ks[(lane & 7) + ((lane >> 4) & 1) * 8]
                                       [((lane >> 3) & 1) * 8]);
    const uint32_t vaddr = smem_u32(&Vs[(lane & 7) + ((lane >> 3) & 1) * 8]
                                       [((lane >> 4) & 1) * 8]);

    const int ntiles = 2 * qb + 2;
    const int qrow0 = q0 + wid * 16 + g;
    const int wmax  = q0 + wid * 16 + 15;

    for (int t = 0; t < ntiles; t++) {
        const int kv0 = t * 64;
        __syncthreads();
        *(uint4*)&Ks[lr][lc]      = kr0;
        *(uint4*)&Ks[lr + 32][lc] = kr1;
        *(uint4*)&Vs[lr][lc]      = vr0;
        *(uint4*)&Vs[lr + 32][lc] = vr1;
        if (t + 1 < ntiles) {
            const int nkv = (t + 1) * 64;
            kr0 = *(const uint4*)(kbase + (size_t)(nkv + lr) * ld + lc);
            kr1 = *(const uint4*)(kbase + (size_t)(nkv + lr + 32) * ld + lc);
            vr0 = *(const uint4*)(vbase + (size_t)(nkv + lr) * ld + lc);
            vr1 = *(const uint4*)(vbase + (size_t)(nkv + lr + 32) * ld + lc);
        }
        __syncthreads();

        if (kv0 > wmax) continue;

        float s[8][4];
        #pragma unroll
        for (int j = 0; j < 8; j++)
            #pragma unroll
            for (int r = 0; r < 4; r++) s[j][r] = 0.0f;
        #pragma unroll
        for (int kk = 0; kk < 4; kk++) {
            uint32_t qa[4];
            LDSM4(qa, qaddr + kk * 32);
            #pragma unroll
            for (int j2 = 0; j2 < 4; j2++) {
                uint32_t kb[4];
                LDSM4(kb, kaddr + j2 * (16 * AST * 2) + kk * 32);
                MMA16816(s[2 * j2],     qa, kb[0], kb[1]);
                MMA16816(s[2 * j2 + 1], qa, kb[2], kb[3]);
            }
        }

        const float scale = 0.125f;
        if (t >= ntiles - 2) {
            #pragma unroll
            for (int j = 0; j < 8; j++) {
                int col = kv0 + j * 8 + c2 * 2;
                s[j][0] = (col     > qrow0)     ? -1e30f : s[j][0] * scale;
                s[j][1] = (col + 1 > qrow0)     ? -1e30f : s[j][1] * scale;
                s[j][2] = (col     > qrow0 + 8) ? -1e30f : s[j][2] * scale;
                s[j][3] = (col + 1 > qrow0 + 8) ? -1e30f : s[j][3] * scale;
            }
        } else {
            #pragma unroll
            for (int j = 0; j < 8; j++)
                #pragma unroll
                for (int r = 0; r < 4; r++) s[j][r] *= scale;
        }

        float mx0 = -1e30f, mx1 = -1e30f;
        #pragma unroll
        for (int j = 0; j < 8; j++) {
            mx0 = fmaxf(mx0, fmaxf(s[j][0], s[j][1]));
            mx1 = fmaxf(mx1, fmaxf(s[j][2], s[j][3]));
        }
        mx0 = fmaxf(mx0, __shfl_xor_sync(0xffffffffu, mx0, 1));
        mx0 = fmaxf(mx0, __shfl_xor_sync(0xffffffffu, mx0, 2));
        mx1 = fmaxf(mx1, __shfl_xor_sync(0xffffffffu, mx1, 1));
        mx1 = fmaxf(mx1, __shfl_xor_sync(0xffffffffu, mx1, 2));
        float mn0 = fmaxf(mrow[0], mx0), mn1 = fmaxf(mrow[1], mx1);
        float fac0 = __expf(mrow[0] - mn0), fac1 = __expf(mrow[1] - mn1);
        float ps0 = 0.0f, ps1 = 0.0f;
        #pragma unroll
        for (int j = 0; j < 8; j++) {
            s[j][0] = __expf(s[j][0] - mn0);
            s[j][1] = __expf(s[j][1] - mn0);
            s[j][2] = __expf(s[j][2] - mn1);
            s[j][3] = __expf(s[j][3] - mn1);
            ps0 += s[j][0] + s[j][1];
            ps1 += s[j][2] + s[j][3];
        }
        ps0 += __shfl_xor_sync(0xffffffffu, ps0, 1);
        ps0 += __shfl_xor_sync(0xffffffffu, ps0, 2);
        ps1 += __shfl_xor_sync(0xffffffffu, ps1, 1);
        ps1 += __shfl_xor_sync(0xffffffffu, ps1, 2);
        lsum[0] = lsum[0] * fac0 + ps0;  mrow[0] = mn0;
        lsum[1] = lsum[1] * fac1 + ps1;  mrow[1] = mn1;
        #pragma unroll
        for (int j = 0; j < 8; j++) {
            o[j][0] *= fac0; o[j][1] *= fac0;
            o[j][2] *= fac1; o[j][3] *= fac1;
        }

        uint32_t pa[4][4];
        #pragma unroll
        for (int kk = 0; kk < 4; kk++) {
            pa[kk][0] = packh2(s[2 * kk][0],     s[2 * kk][1]);
            pa[kk][1] = packh2(s[2 * kk][2],     s[2 * kk][3]);
            pa[kk][2] = packh2(s[2 * kk + 1][0], s[2 * kk + 1][1]);
            pa[kk][3] = packh2(s[2 * kk + 1][2], s[2 * kk + 1][3]);
        }

        #pragma unroll
        for (int j2 = 0; j2 < 4; j2++) {
            #pragma unroll
            for (int kk = 0; kk < 4; kk++) {
                uint32_t vb[4];
                LDSM4T(vb, vaddr + kk * (16 * AST * 2) + j2 * 32);
                MMA16816(o[2 * j2],     pa[kk], vb[0], vb[1]);
                MMA16816(o[2 * j2 + 1], pa[kk], vb[2], vb[3]);
            }
        }
    }

    float inv0 = 1.0f / lsum[0], inv1 = 1.0f / lsum[1];
    const size_t rbase0 = ((size_t)(b * SEQ) + qrow0) * BDIM + hd * DHEAD;
    const size_t rbase1 = rbase0 + (size_t)8 * BDIM;
    #pragma unroll
    for (int j = 0; j < 8; j++) {
        int col = j * 8 + c2 * 2;
        *(__half2*)(outh + rbase0 + col) = __floats2half2_rn(o[j][0] * inv0, o[j][1] * inv0);
        *(__half2*)(outh + rbase1 + col) = __floats2half2_rn(o[j][2] * inv1, o[j][3] * inv1);
    }
}

// ===================== launch ==============================================
extern "C" void kernel_launch(void* const* d_in, const int* in_sizes, int n_in,
                              void* d_out, int out_size)
{
    const float* x      = (const float*)d_in[0];
    const float* w_qkv  = (const float*)d_in[1];
    const float* w_o    = (const float*)d_in[2];
    const float* w_up   = (const float*)d_in[3];
    const float* w_gate = (const float*)d_in[4];
    const float* w_down = (const float*)d_in[5];
    const float* scale1 = (const float*)d_in[6];
    const float* scale2 = (const float*)d_in[7];
    float* out = (float*)d_out;

    float *x1;
    __half *qkvh, *xnh, *ath, *hh;
    __half *wqkvh, *woh, *wuph, *wgh, *wdh;
    cudaGetSymbolAddress((void**)&x1,   g_x1);
    cudaGetSymbolAddress((void**)&qkvh, g_qkvh);
    cudaGetSymbolAddress((void**)&xnh, g_xnh);
    cudaGetSymbolAddress((void**)&ath, g_ath);
    cudaGetSymbolAddress((void**)&hh,  g_hh);
    cudaGetSymbolAddress((void**)&wqkvh, g_wqkvh);
    cudaGetSymbolAddress((void**)&woh, g_woh);
    cudaGetSymbolAddress((void**)&wuph, g_wuph);
    cudaGetSymbolAddress((void**)&wgh, g_wgh);
    cudaGetSymbolAddress((void**)&wdh, g_wdh);

    cudaFuncSetAttribute(gemm_hmma<1>,
                         cudaFuncAttributeMaxDynamicSharedMemorySize, GEMM_SMEM);
    cudaFuncSetAttribute(gemm_hmma<3>,
                         cudaFuncAttributeMaxDynamicSharedMemorySize, GEMM_SMEM);
    cudaFuncSetAttribute(gemm_upgate,
                         cudaFuncAttributeMaxDynamicSharedMemorySize, UG_SMEM);

    // 0. all weight converts in one launch
    cvt_all<<<(CX4 + 255) / 256, 256>>>(w_qkv, w_o, w_up, w_gate, w_down,
                                        wqkvh, woh, wuph, wgh, wdh);

    // 1. xn = rmsnorm(x, scale1) -> fp16
    rmsnorm_h<<<NTOK, 256>>>(x, scale1, xnh);

    // 2. qkvh = fp16(xn @ w_qkv.T)
    {
        dim3 g(3 * BDIM / BN, NTOK / BM);
        gemm_hmma<3><<<g, 256, GEMM_SMEM>>>(xnh, wqkvh, nullptr, nullptr, qkvh,
                                            NTOK, 3 * BDIM, BDIM);
    }

    // 3. attention core -> ath (fp16)
    {
        dim3 g(SEQ / 128, NHEAD, BATCH);
        flash_attn_h<<<g, 256>>>(qkvh, ath);
    }

    // 4. x1 = x + attn @ w_o.T
    {
        dim3 g(BDIM / BN, NTOK / BM);
        gemm_hmma<1><<<g, 256, GEMM_SMEM>>>(ath, woh, x1, x, nullptr,
                                            NTOK, BDIM, BDIM);
    }

    // 5. xn = rmsnorm(x1, scale2) -> fp16
    rmsnorm_h<<<NTOK, 256>>>(x1, scale2, xnh);

    // 6+7. hh = (xn @ w_up.T) * silu(xn @ w_gate.T)  (fused, fp16)
    {
        dim3 g(HID / UGN, NTOK / BM);
        gemm_upgate<<<g, 256, UG_SMEM>>>(xnh, wuph, wgh, hh, NTOK, HID, BDIM);
    }

    // 8. out = x1 + hh @ w_down.T
    {
        dim3 g(BDIM / BN, NTOK / BM);
        gemm_hmma<1><<<g, 256, GEMM_SMEM>>>(hh, wdh, out, x1, nullptr,
                                            NTOK, BDIM, HID);
    }
}

// round 17
// speedup vs baseline: 1.5382x; 1.5382x over previous
#include <cuda_runtime.h>
#include <cuda_fp16.h>
#include <cstdint>
#include <math.h>

#define BDIM   1024
#define NHEAD  16
#define DHEAD  64
#define SEQ    2048
#define BATCH  2
#define NTOK   (BATCH * SEQ)      // 4096
#define HID    (4 * BDIM)         // 4096
#define EPSV   1e-6f

// ===================== helpers =============================================
__device__ __forceinline__ uint32_t smem_u32(const void* p) {
    uint32_t a;
    asm("{ .reg .u64 t; cvta.to.shared.u64 t, %1; cvt.u32.u64 %0, t; }"
        : "=r"(a) : "l"(p));
    return a;
}

#define CP_ASYNC16(s, g) \
    asm volatile("cp.async.cg.shared.global [%0], [%1], 16;" :: "r"(s), "l"(g))
#define CP_COMMIT()  asm volatile("cp.async.commit_group;" ::: "memory")
#define CP_WAIT1()   asm volatile("cp.async.wait_group 1;" ::: "memory")

#define LDSM4(r, a) \
    asm volatile("ldmatrix.sync.aligned.m8n8.x4.shared.b16 {%0,%1,%2,%3}, [%4];" \
        : "=r"((r)[0]), "=r"((r)[1]), "=r"((r)[2]), "=r"((r)[3]) : "r"(a))
#define LDSM4T(r, a) \
    asm volatile("ldmatrix.sync.aligned.m8n8.x4.trans.shared.b16 {%0,%1,%2,%3}, [%4];" \
        : "=r"((r)[0]), "=r"((r)[1]), "=r"((r)[2]), "=r"((r)[3]) : "r"(a))

#define MMA16816(d, a, b0, b1) \
    asm volatile("mma.sync.aligned.m16n8k16.row.col.f32.f16.f16.f32 " \
        "{%0,%1,%2,%3}, {%4,%5,%6,%7}, {%8,%9}, {%0,%1,%2,%3};" \
        : "+f"((d)[0]), "+f"((d)[1]), "+f"((d)[2]), "+f"((d)[3]) \
        : "r"((a)[0]), "r"((a)[1]), "r"((a)[2]), "r"((a)[3]), "r"(b0), "r"(b1))

__device__ __forceinline__ uint32_t packh2(float a, float b) {
    __half2 h = __floats2half2_rn(a, b);
    return *(uint32_t*)&h;
}

// ===================== scratch ==============================================
__device__ float g_x1 [(size_t)NTOK * BDIM];
__device__ unsigned short g_qkvh[(size_t)NTOK * 3 * BDIM];
__device__ unsigned short g_xnh[(size_t)NTOK * BDIM];
__device__ unsigned short g_ath[(size_t)NTOK * BDIM];
__device__ unsigned short g_hh [(size_t)NTOK * HID];
__device__ unsigned short g_wqkvh[(size_t)3 * BDIM * BDIM];
__device__ unsigned short g_woh[(size_t)BDIM * BDIM];
__device__ unsigned short g_wuph[(size_t)HID * BDIM];
__device__ unsigned short g_wgh [(size_t)HID * BDIM];
__device__ unsigned short g_wdh [(size_t)BDIM * HID];

// ===================== fused weight convert fp32 -> fp16 (16 elems/thread) ==
#define CX0 196608
#define CX1 (CX0 + 65536)
#define CX2 (CX1 + 262144)
#define CX3 (CX2 + 262144)
#define CX4 (CX3 + 262144)

__global__ void cvt_all(const float* __restrict__ wq, const float* __restrict__ wo,
                        const float* __restrict__ wu, const float* __restrict__ wg,
                        const float* __restrict__ wd,
                        __half* __restrict__ oq, __half* __restrict__ oo,
                        __half* __restrict__ ou, __half* __restrict__ og,
                        __half* __restrict__ od)
{
    int u = blockIdx.x * blockDim.x + threadIdx.x;
    if (u >= CX4) return;
    const float* in; __half* out; int base;
    if      (u < CX0) { in = wq; out = oq; base = 0;   }
    else if (u < CX1) { in = wo; out = oo; base = CX0; }
    else if (u < CX2) { in = wu; out = ou; base = CX1; }
    else if (u < CX3) { in = wg; out = og; base = CX2; }
    else              { in = wd; out = od; base = CX3; }
    int i16 = (u - base) * 16;
    float4 a = *(const float4*)(in + i16);
    float4 b = *(const float4*)(in + i16 + 4);
    float4 c = *(const float4*)(in + i16 + 8);
    float4 d = *(const float4*)(in + i16 + 12);
    uint4 o0, o1;
    o0.x = packh2(a.x, a.y); o0.y = packh2(a.z, a.w);
    o0.z = packh2(b.x, b.y); o0.w = packh2(b.z, b.w);
    o1.x = packh2(c.x, c.y); o1.y = packh2(c.z, c.w);
    o1.z = packh2(d.x, d.y); o1.w = packh2(d.z, d.w);
    *(uint4*)(out + i16)     = o0;
    *(uint4*)(out + i16 + 8) = o1;
}

// ===================== rmsnorm -> fp16 ======================================
__global__ void rmsnorm_h(const float* __restrict__ x,
                          const float* __restrict__ scale,
                          __half* __restrict__ ohi)
{
    int row = blockIdx.x;
    float4 v = ((const float4*)(x + (size_t)row * BDIM))[threadIdx.x];
    float ss = v.x * v.x + v.y * v.y + v.z * v.z + v.w * v.w;
    #pragma unroll
    for (int o = 16; o > 0; o >>= 1) ss += __shfl_xor_sync(0xffffffffu, ss, o);
    __shared__ float ws[8];
    if ((threadIdx.x & 31) == 0) ws[threadIdx.x >> 5] = ss;
    __syncthreads();
    float tot = ws[0] + ws[1] + ws[2] + ws[3] + ws[4] + ws[5] + ws[6] + ws[7];
    float inv = 1.0f / sqrtf(tot * (1.0f / BDIM) + EPSV);
    float4 sc = ((const float4*)scale)[threadIdx.x];
    size_t off = (size_t)row * BDIM + threadIdx.x * 4;
    *(__half2*)(ohi + off)     = __floats2half2_rn(v.x * inv * sc.x, v.y * inv * sc.y);
    *(__half2*)(ohi + off + 2) = __floats2half2_rn(v.z * inv * sc.z, v.w * inv * sc.w);
}

// ===================== HMMA fp16 GEMM (2 CTAs/SM, 3-stage) ==================
// C[M,N] = Ah[M,K] * Bh[N,K]^T ; fp32 accum.
// EPI 1: C(fp32) = acc + R ; EPI 3: O1(fp16) = acc
#define BM 128
#define BN 128
#define BKE 32
#define LDSB 80
#define BUF_B (BM * LDSB)           // 10240
#define STG_B (2 * BUF_B)           // 20480
#define NSTAGE 3
#define GEMM_SMEM (NSTAGE * STG_B)  // 61440

template<int EPI>
__global__ __launch_bounds__(256, 2)
void gemm_hmma(const __half* __restrict__ Ah, const __half* __restrict__ Bh,
               float* __restrict__ C, const float* __restrict__ R,
               __half* __restrict__ O1,
               int M, int N, int K)
{
    extern __shared__ char smem[];
    const uint32_t sb = smem_u32(smem);

    const int tid  = threadIdx.x;
    const int lane = tid & 31;
    const int wid  = tid >> 5;
    const int wm   = wid & 3;
    const int wn   = wid >> 2;
    const int bm = blockIdx.y * BM, bn = blockIdx.x * BN;

    const __half* gptr[2][2];
    uint32_t      sptr[2][2];
    {
        const __half* gsrc[2] = {Ah, Bh};
        #pragma unroll
        for (int q = 0; q < 2; q++) {
            int rbase = (q == 0) ? bm : bn;
            #pragma unroll
            for (int j = 0; j < 2; j++) {
                int idx = tid * 2 + j;
                int row = idx >> 2, kc = idx & 3;
                gptr[q][j] = gsrc[q] + (size_t)(rbase + row) * K + kc * 8;
                sptr[q][j] = sb + q * BUF_B + row * LDSB + kc * 16;
            }
        }
    }

    const int nch = K / BKE;

    #pragma unroll
    for (int s = 0; s < NSTAGE - 1; s++) {
        #pragma unroll
        for (int q = 0; q < 2; q++)
            #pragma unroll
            for (int j = 0; j < 2; j++)
                CP_ASYNC16(sptr[q][j] + s * STG_B, gptr[q][j] + s * BKE);
        CP_COMMIT();
    }

    const uint32_t pA = sb + (wm * 32 + (lane & 15)) * LDSB + ((lane >> 4) * 8) * 2;
    const int b_n = (lane & 7) + ((lane >> 4) & 1) * 8;
    const int b_k = ((lane >> 3) & 1) * 8;
    const uint32_t pB = sb + BUF_B + (wn * 64 + b_n) * LDSB + b_k * 2;

    float acc[2][8][4];
    #pragma unroll
    for (int i = 0; i < 2; i++)
        #pragma unroll
        for (int j = 0; j < 8; j++)
            #pragma unroll
            for (int r = 0; r < 4; r++) acc[i][j][r] = 0.0f;

    for (int c = 0; c < nch; c++) {
        CP_WAIT1();
        __syncthreads();

        const int cn = c + NSTAGE - 1;
        if (cn < nch) {
            const uint32_t sw = (cn % NSTAGE) * STG_B;
            #pragma unroll
            for (int q = 0; q < 2; q++)
                #pragma unroll
                for (int j = 0; j < 2; j++)
                    CP_ASYNC16(sptr[q][j] + sw, gptr[q][j] + cn * BKE);
        }
        CP_COMMIT();

        const uint32_t so = (c % NSTAGE) * STG_B;
        #pragma unroll
        for (int ks = 0; ks < 2; ks++) {
            uint32_t ah[2][4], bh[4][4];
            #pragma unroll
            for (int i = 0; i < 2; i++)
                LDSM4(ah[i], pA + so + i * (16 * LDSB) + ks * 32);
            #pragma unroll
            for (int j2 = 0; j2 < 4; j2++)
                LDSM4(bh[j2], pB + so + j2 * (16 * LDSB) + ks * 32);
            #pragma unroll
            for (int i = 0; i < 2; i++)
                #pragma unroll
                for (int j = 0; j < 8; j++) {
                    const int j2 = j >> 1, hh = (j & 1) * 2;
                    MMA16816(acc[i][j], ah[i], bh[j2][hh], bh[j2][hh + 1]);
                }
        }
    }

    const int g  = lane >> 2;
    const int c2 = (lane & 3) * 2;
    #pragma unroll
    for (int i = 0; i < 2; i++) {
        #pragma unroll
        for (int j = 0; j < 8; j++) {
            const int col = bn + wn * 64 + j * 8 + c2;
            const int r0 = bm + wm * 32 + i * 16 + g;
            #pragma unroll
            for (int hrow = 0; hrow < 2; hrow++) {
                const int row = r0 + hrow * 8;
                const size_t base = (size_t)row * N + col;
                float v0 = acc[i][j][hrow * 2 + 0];
                float v1 = acc[i][j][hrow * 2 + 1];
                if (EPI == 1) {
                    float2 rv = *(const float2*)(R + base);
                    *(float2*)(C + base) = make_float2(v0 + rv.x, v1 + rv.y);
                } else {
                    *(__half2*)(O1 + base) = __floats2half2_rn(v0, v1);
                }
            }
        }
    }
}

// ===================== fused up+gate GEMM (BN=64, 2 CTAs/SM, 3-stage) =======
#define UGN 64
#define UG_ABUF (BM * LDSB)                 // 10240
#define UG_BBUF (UGN * LDSB)                // 5120
#define UG_STG  (UG_ABUF + 2 * UG_BBUF)     // 20480
#define UG_NSTG 3
#define UG_SMEM (UG_NSTG * UG_STG)          // 61440

__global__ __launch_bounds__(256, 2)
void gemm_upgate(const __half* __restrict__ Ah, const __half* __restrict__ Bu,
                 const __half* __restrict__ Bg, __half* __restrict__ O1,
                 int M, int N, int K)
{
    extern __shared__ char smem[];
    const uint32_t sb = smem_u32(smem);

    const int tid  = threadIdx.x;
    const int lane = tid & 31;
    const int wid  = tid >> 5;
    const int wm   = wid & 3;
    const int wn   = wid >> 2;
    const int bm = blockIdx.y * BM, bn = blockIdx.x * UGN;

    const __half* gA[2]; uint32_t sA[2];
    #pragma unroll
    for (int j = 0; j < 2; j++) {
        int idx = tid * 2 + j;
        int row = idx >> 2, kc = idx & 3;
        gA[j] = Ah + (size_t)(bm + row) * K + kc * 8;
        sA[j] = sb + row * LDSB + kc * 16;
    }
    const int brow = tid >> 2, bkc = tid & 3;
    const __half* gBu = Bu + (size_t)(bn + brow) * K + bkc * 8;
    const __half* gBg = Bg + (size_t)(bn + brow) * K + bkc * 8;
    const uint32_t sBu = sb + UG_ABUF + brow * LDSB + bkc * 16;
    const uint32_t sBg = sb + UG_ABUF + UG_BBUF + brow * LDSB + bkc * 16;

    const int nch = K / BKE;

    #pragma unroll
    for (int s = 0; s < UG_NSTG - 1; s++) {
        #pragma unroll
        for (int j = 0; j < 2; j++) CP_ASYNC16(sA[j] + s * UG_STG, gA[j] + s * BKE);
        CP_ASYNC16(sBu + s * UG_STG, gBu + s * BKE);
        CP_ASYNC16(sBg + s * UG_STG, gBg + s * BKE);
        CP_COMMIT();
    }

    const uint32_t pA = sb + (wm * 32 + (lane & 15)) * LDSB + ((lane >> 4) * 8) * 2;
    const int b_n = (lane & 7) + ((lane >> 4) & 1) * 8;
    const int b_k = ((lane >> 3) & 1) * 8;
    const uint32_t pBu = sb + UG_ABUF + (wn * 32 + b_n) * LDSB + b_k * 2;
    const uint32_t pBg = pBu + UG_BBUF;

    float au[2][4][4], ag[2][4][4];
    #pragma unroll
    for (int i = 0; i < 2; i++)
        #pragma unroll
        for (int j = 0; j < 4; j++)
            #pragma unroll
            for (int r = 0; r < 4; r++) { au[i][j][r] = 0.0f; ag[i][j][r] = 0.0f; }

    for (int c = 0; c < nch; c++) {
        CP_WAIT1();
        __syncthreads();

        const int cn = c + UG_NSTG - 1;
        if (cn < nch) {
            const uint32_t sw = (cn % UG_NSTG) * UG_STG;
            #pragma unroll
            for (int j = 0; j < 2; j++) CP_ASYNC16(sA[j] + sw, gA[j] + cn * BKE);
            CP_ASYNC16(sBu + sw, gBu + cn * BKE);
            CP_ASYNC16(sBg + sw, gBg + cn * BKE);
        }
        CP_COMMIT();

        const uint32_t so = (c % UG_NSTG) * UG_STG;
        #pragma unroll
        for (int ks = 0; ks < 2; ks++) {
            uint32_t ah[2][4], bu[2][4], bg[2][4];
            #pragma unroll
            for (int i = 0; i < 2; i++)
                LDSM4(ah[i], pA + so + i * (16 * LDSB) + ks * 32);
            #pragma unroll
            for (int j2 = 0; j2 < 2; j2++) {
                LDSM4(bu[j2], pBu + so + j2 * (16 * LDSB) + ks * 32);
                LDSM4(bg[j2], pBg + so + j2 * (16 * LDSB) + ks * 32);
            }
            #pragma unroll
            for (int i = 0; i < 2; i++)
                #pragma unroll
                for (int j = 0; j < 4; j++) {
                    const int j2 = j >> 1, hh = (j & 1) * 2;
                    MMA16816(au[i][j], ah[i], bu[j2][hh], bu[j2][hh + 1]);
                    MMA16816(ag[i][j], ah[i], bg[j2][hh], bg[j2][hh + 1]);
                }
        }
    }

    const int g  = lane >> 2;
    const int c2 = (lane & 3) * 2;
    #pragma unroll
    for (int i = 0; i < 2; i++) {
        #pragma unroll
        for (int j = 0; j < 4; j++) {
            const int col = bn + wn * 32 + j * 8 + c2;
            const int r0 = bm + wm * 32 + i * 16 + g;
            #pragma unroll
            for (int hrow = 0; hrow < 2; hrow++) {
                const int row = r0 + hrow * 8;
                const size_t base = (size_t)row * N + col;
                float u0 = au[i][j][hrow * 2 + 0], u1 = au[i][j][hrow * 2 + 1];
                float g0 = ag[i][j][hrow * 2 + 0], g1 = ag[i][j][hrow * 2 + 1];
                float s0 = u0 * (g0 / (1.0f + __expf(-g0)));
                float s1 = u1 * (g1 / (1.0f + __expf(-g1)));
                *(__half2*)(O1 + base) = __floats2half2_rn(s0, s1);
            }
        }
    }
}

// ===================== fp16 HMMA flash attention (reg prefetch) =============
#define AST 72

__global__ __launch_bounds__(256)
void flash_attn_h(const __half* __restrict__ qkvh, __half* __restrict__ outh)
{
    __shared__ __half Qs[128][AST];
    __shared__ __half Ks[64][AST];
    __shared__ __half Vs[64][AST];

    const int qb = gridDim.x - 1 - blockIdx.x;
    const int hd = blockIdx.y, b = blockIdx.z;
    const int q0 = qb * 128;
    const int tid = threadIdx.x, lane = tid & 31, wid = tid >> 5;
    const int ld = 3 * BDIM;
    const int g = lane >> 2, c2 = lane & 3;

    const __half* qbase = qkvh + ((size_t)(b * SEQ + q0)) * ld + hd * DHEAD;
    #pragma unroll
    for (int i = 0; i < 4; i++) {
        int idx = tid + i * 256;
        int r = idx >> 3, c8 = (idx & 7) * 8;
        *(uint4*)&Qs[r][c8] = *(const uint4*)(qbase + (size_t)r * ld + c8);
    }

    const __half* kbase = qkvh + (size_t)(b * SEQ) * ld + BDIM     + hd * DHEAD;
    const __half* vbase = qkvh + (size_t)(b * SEQ) * ld + 2 * BDIM + hd * DHEAD;

    const int lr = tid >> 3;
    const int lc = (tid & 7) * 8;

    uint4 kr0 = *(const uint4*)(kbase + (size_t)lr * ld + lc);
    uint4 kr1 = *(const uint4*)(kbase + (size_t)(lr + 32) * ld + lc);
    uint4 vr0 = *(const uint4*)(vbase + (size_t)lr * ld + lc);
    uint4 vr1 = *(const uint4*)(vbase + (size_t)(lr + 32) * ld + lc);

    float o[8][4];
    #pragma unroll
    for (int j = 0; j < 8; j++)
        #pragma unroll
        for (int r = 0; r < 4; r++) o[j][r] = 0.0f;
    float mrow[2] = {-1e30f, -1e30f}, lsum[2] = {0.0f, 0.0f};

    const uint32_t qaddr = smem_u32(&Qs[wid * 16 + (lane & 15)][(lane >> 4) * 8]);
    const uint32_t kaddr = smem_u32(&Ks[(lane & 7) + ((lane >> 4) & 1) * 8]
                                       [((lane >> 3) & 1) * 8]);
    const uint32_t vaddr = smem_u32(&Vs[(lane & 7) + ((lane >> 3) & 1) * 8]
                                       [((lane >> 4) & 1) * 8]);

    const int ntiles = 2 * qb + 2;
    const int qrow0 = q0 + wid * 16 + g;
    const int wmax  = q0 + wid * 16 + 15;

    for (int t = 0; t < ntiles; t++) {
        const int kv0 = t * 64;
        __syncthreads();
        *(uint4*)&Ks[lr][lc]      = kr0;
        *(uint4*)&Ks[lr + 32][lc] = kr1;
        *(uint4*)&Vs[lr][lc]      = vr0;
        *(uint4*)&Vs[lr + 32][lc] = vr1;
        if (t + 1 < ntiles) {
            const int nkv = (t + 1) * 64;
            kr0 = *(const uint4*)(kbase + (size_t)(nkv + lr) * ld + lc);
            kr1 = *(const uint4*)(kbase + (size_t)(nkv + lr + 32) * ld + lc);
            vr0 = *(const uint4*)(vbase + (size_t)(nkv + lr) * ld + lc);
            vr1 = *(const uint4*)(vbase + (size_t)(nkv + lr + 32) * ld + lc);
        }
        __syncthreads();

        if (kv0 > wmax) continue;

        float s[8][4];
        #pragma unroll
        for (int j = 0; j < 8; j++)
            #pragma unroll
            for (int r = 0; r < 4; r++) s[j][r] = 0.0f;
        #pragma unroll
        for (int kk = 0; kk < 4; kk++) {
            uint32_t qa[4];
            LDSM4(qa, qaddr + kk * 32);
            #pragma unroll
            for (int j2 = 0; j2 < 4; j2++) {
                uint32_t kb[4];
                LDSM4(kb, kaddr + j2 * (16 * AST * 2) + kk * 32);
                MMA16816(s[2 * j2],     qa, kb[0], kb[1]);
                MMA16816(s[2 * j2 + 1], qa, kb[2], kb[3]);
            }
        }

        const float scale = 0.125f;
        if (t >= ntiles - 2) {
            #pragma unroll
            for (int j = 0; j < 8; j++) {
                int col = kv0 + j * 8 + c2 * 2;
                s[j][0] = (col     > qrow0)     ? -1e30f : s[j][0] * scale;
                s[j][1] = (col + 1 > qrow0)     ? -1e30f : s[j][1] * scale;
                s[j][2] = (col     > qrow0 + 8) ? -1e30f : s[j][2] * scale;
                s[j][3] = (col + 1 > qrow0 + 8) ? -1e30f : s[j][3] * scale;
            }
        } else {
            #pragma unroll
            for (int j = 0; j < 8; j++)
                #pragma unroll
                for (int r = 0; r < 4; r++) s[j][r] *= scale;
        }

        float mx0 = -1e30f, mx1 = -1e30f;
        #pragma unroll
        for (int j = 0; j < 8; j++) {
            mx0 = fmaxf(mx0, fmaxf(s[j][0], s[j][1]));
            mx1 = fmaxf(mx1, fmaxf(s[j][2], s[j][3]));
        }
        mx0 = fmaxf(mx0, __shfl_xor_sync(0xffffffffu, mx0, 1));
        mx0 = fmaxf(mx0, __shfl_xor_sync(0xffffffffu, mx0, 2));
        mx1 = fmaxf(mx1, __shfl_xor_sync(0xffffffffu, mx1, 1));
        mx1 = fmaxf(mx1, __shfl_xor_sync(0xffffffffu, mx1, 2));
        float mn0 = fmaxf(mrow[0], mx0), mn1 = fmaxf(mrow[1], mx1);
        float fac0 = __expf(mrow[0] - mn0), fac1 = __expf(mrow[1] - mn1);
        float ps0 = 0.0f, ps1 = 0.0f;
        #pragma unroll
        for (int j = 0; j < 8; j++) {
            s[j][0] = __expf(s[j][0] - mn0);
            s[j][1] = __expf(s[j][1] - mn0);
            s[j][2] = __expf(s[j][2] - mn1);
            s[j][3] = __expf(s[j][3] - mn1);
            ps0 += s[j][0] + s[j][1];
            ps1 += s[j][2] + s[j][3];
        }
        ps0 += __shfl_xor_sync(0xffffffffu, ps0, 1);
        ps0 += __shfl_xor_sync(0xffffffffu, ps0, 2);
        ps1 += __shfl_xor_sync(0xffffffffu, ps1, 1);
        ps1 += __shfl_xor_sync(0xffffffffu, ps1, 2);
        lsum[0] = lsum[0] * fac0 + ps0;  mrow[0] = mn0;
        lsum[1] = lsum[1] * fac1 + ps1;  mrow[1] = mn1;
        #pragma unroll
        for (int j = 0; j < 8; j++) {
            o[j][0] *= fac0; o[j][1] *= fac0;
            o[j][2] *= fac1; o[j][3] *= fac1;
        }

        uint32_t pa[4][4];
        #pragma unroll
        for (int kk = 0; kk < 4; kk++) {
            pa[kk][0] = packh2(s[2 * kk][0],     s[2 * kk][1]);
            pa[kk][1] = packh2(s[2 * kk][2],     s[2 * kk][3]);
            pa[kk][2] = packh2(s[2 * kk + 1][0], s[2 * kk + 1][1]);
            pa[kk][3] = packh2(s[2 * kk + 1][2], s[2 * kk + 1][3]);
        }

        #pragma unroll
        for (int j2 = 0; j2 < 4; j2++) {
            #pragma unroll
            for (int kk = 0; kk < 4; kk++) {
                uint32_t vb[4];
                LDSM4T(vb, vaddr + kk * (16 * AST * 2) + j2 * 32);
                MMA16816(o[2 * j2],     pa[kk], vb[0], vb[1]);
                MMA16816(o[2 * j2 + 1], pa[kk], vb[2], vb[3]);
            }
        }
    }

    float inv0 = 1.0f / lsum[0], inv1 = 1.0f / lsum[1];
    const size_t rbase0 = ((size_t)(b * SEQ) + qrow0) * BDIM + hd * DHEAD;
    const size_t rbase1 = rbase0 + (size_t)8 * BDIM;
    #pragma unroll
    for (int j = 0; j < 8; j++) {
        int col = j * 8 + c2 * 2;
        *(__half2*)(outh + rbase0 + col) = __floats2half2_rn(o[j][0] * inv0, o[j][1] * inv0);
        *(__half2*)(outh + rbase1 + col) = __floats2half2_rn(o[j][2] * inv1, o[j][3] * inv1);
    }
}

// ===================== launch ==============================================
extern "C" void kernel_launch(void* const* d_in, const int* in_sizes, int n_in,
                              void* d_out, int out_size)
{
    const float* x      = (const float*)d_in[0];
    const float* w_qkv  = (const float*)d_in[1];
    const float* w_o    = (const float*)d_in[2];
    const float* w_up   = (const float*)d_in[3];
    const float* w_gate = (const float*)d_in[4];
    const float* w_down = (const float*)d_in[5];
    const float* scale1 = (const float*)d_in[6];
    const float* scale2 = (const float*)d_in[7];
    float* out = (float*)d_out;

    float *x1;
    __half *qkvh, *xnh, *ath, *hh;
    __half *wqkvh, *woh, *wuph, *wgh, *wdh;
    cudaGetSymbolAddress((void**)&x1,   g_x1);
    cudaGetSymbolAddress((void**)&qkvh, g_qkvh);
    cudaGetSymbolAddress((void**)&xnh, g_xnh);
    cudaGetSymbolAddress((void**)&ath, g_ath);
    cudaGetSymbolAddress((void**)&hh,  g_hh);
    cudaGetSymbolAddress((void**)&wqkvh, g_wqkvh);
    cudaGetSymbolAddress((void**)&woh, g_woh);
    cudaGetSymbolAddress((void**)&wuph, g_wuph);
    cudaGetSymbolAddress((void**)&wgh, g_wgh);
    cudaGetSymbolAddress((void**)&wdh, g_wdh);

    cudaFuncSetAttribute(gemm_hmma<1>,
                         cudaFuncAttributeMaxDynamicSharedMemorySize, GEMM_SMEM);
    cudaFuncSetAttribute(gemm_hmma<3>,
                         cudaFuncAttributeMaxDynamicSharedMemorySize, GEMM_SMEM);
    cudaFuncSetAttribute(gemm_upgate,
                         cudaFuncAttributeMaxDynamicSharedMemorySize, UG_SMEM);

    // 0. all weight converts in one launch
    cvt_all<<<(CX4 + 255) / 256, 256>>>(w_qkv, w_o, w_up, w_gate, w_down,
                                        wqkvh, woh, wuph, wgh, wdh);

    // 1. xn = rmsnorm(x, scale1) -> fp16
    rmsnorm_h<<<NTOK, 256>>>(x, scale1, xnh);

    // 2. qkvh = fp16(xn @ w_qkv.T)
    {
        dim3 g(3 * BDIM / BN, NTOK / BM);
        gemm_hmma<3><<<g, 256, GEMM_SMEM>>>(xnh, wqkvh, nullptr, nullptr, qkvh,
                                            NTOK, 3 * BDIM, BDIM);
    }

    // 3. attention core -> ath (fp16)
    {
        dim3 g(SEQ / 128, NHEAD, BATCH);
        flash_attn_h<<<g, 256>>>(qkvh, ath);
    }

    // 4. x1 = x + attn @ w_o.T
    {
        dim3 g(BDIM / BN, NTOK / BM);
        gemm_hmma<1><<<g, 256, GEMM_SMEM>>>(ath, woh, x1, x, nullptr,
                                            NTOK, BDIM, BDIM);
    }

    // 5. xn = rmsnorm(x1, scale2) -> fp16
    rmsnorm_h<<<NTOK, 256>>>(x1, scale2, xnh);

    // 6+7. hh = (xn @ w_up.T) * silu(xn @ w_gate.T)  (fused, fp16)
    {
        dim3 g(HID / UGN, NTOK / BM);
        gemm_upgate<<<g, 256, UG_SMEM>>>(xnh, wuph, wgh, hh, NTOK, HID, BDIM);
    }

    // 8. out = x1 + hh @ w_down.T
    {
        dim3 g(BDIM / BN, NTOK / BM);
        gemm_hmma<1><<<g, 256, GEMM_SMEM>>>(hh, wdh, out, x1, nullptr,
                                            NTOK, BDIM, HID);
    }
}